// round 4
// baseline (speedup 1.0000x reference)
#include <cuda_runtime.h>
#include <cuda_bf16.h>

// Holt-Winters (no trend), last n_preds columns only.
// smooth_t = a*(x_t/s_t) + b*smooth_{t-1}, b = 1-a; out_t = smooth_t * s_t.
// Closed form: smooth_{t0} = sum_j a*b^(t0-j)*(x_j/s_j) + b^(t0+1)*x_0.
// Ages d with a*b^d < 1e-11 vanish in a float32 sum of O(1) terms; the sum is
// truncated to a window of <= 256 newest samples (cutoff computed from b).
//
// ONE row per warp, 8 elements per lane (2 x LDG.128, window=256).
// Lane weights a*b^d built by exact squaring. After the xor-reduce gives
// smooth_{t0} to every lane, the NP predictions come from a closed-form
// warp prefix scan:
//   smooth_{t0+1+p} = b^p * ( b*S0 + sum_{i<=p} y_i * b^-i ),  y_i = a*x_i/s_i
// computed with 4 shfl_up steps and stored coalesced by lanes 0..NP-1.

#define WARPS_PER_BLOCK 8
#define THREADS (WARPS_PER_BLOCK * 32)
#define WINDOW 256
#define MAX_SLEN 16

__global__ __launch_bounds__(THREADS)
void hw_notrend_kernel(const float* __restrict__ series,
                       const int*   __restrict__ shifts,
                       const float* __restrict__ alpha_p,
                       const float* __restrict__ init_season,
                       float*       __restrict__ out,
                       int B, int T, int slen, int NP)
{
    __shared__ float sh_inv[WARPS_PER_BLOCK][33];      // inv season, period-extended
    __shared__ float sh_s[WARPS_PER_BLOCK][MAX_SLEN];  // season values

    const int lane = threadIdx.x & 31;
    const int wloc = threadIdx.x >> 5;
    const int row  = blockIdx.x * WARPS_PER_BLOCK + wloc;
    if (row >= B) return;

    const float alpha = __ldg(alpha_p);
    const float b = 1.0f - alpha;

    // ---- per-row seasonal tables (32 lanes fill 33 entries) ----
    {
        int shift = __ldg(&shifts[row]);
        int p = lane;
        int ph  = p % slen;
        int idx = ph - shift; idx %= slen; if (idx < 0) idx += slen;
        float sv = __ldg(&init_season[idx]);
        sh_inv[wloc][p] = __fdividef(1.0f, sv);
        if (p < slen) sh_s[wloc][p] = sv;
        if (lane == 0) {
            int idx32 = (32 % slen) - shift; idx32 %= slen; if (idx32 < 0) idx32 += slen;
            sh_inv[wloc][32] = __fdividef(1.0f, __ldg(&init_season[idx32]));
        }
    }
    __syncwarp();

    const int t0   = T - 1 - NP;                // target: smooth_{t0}
    const int jend = (t0 + 1 + 3) & ~3;         // align-up(t0+1, 4)
    const int e0   = jend - t0 - 1;             // 0..3
    const int jlo  = jend - 8 * (lane + 1);     // this lane's 8-elem chunk (16B aligned)
    const int d0   = 8 * lane - e0;             // smallest age in chunk

    // Age cutoff: b^d < 1e-11  <=>  d > ln(1e-11)/ln(b)  (capped by window).
    const float lb = __logf(b);
    int dcut = WINDOW;
    if (lb < -1e-9f) {
        int c = (int)(-25.328436f / lb) + 1;
        if (c < dcut) dcut = c;
    }

    const float* __restrict__ xrow = series + (size_t)row * (size_t)T;

    float acc = 0.0f;
    if (d0 <= dcut) {
        // ---- 8 elements: 2 x float4 (aligned) or guarded scalar path ----
        float xs[8];
        if (jlo >= 0 && jlo + 8 <= T) {
            const float4* p4 = (const float4*)(xrow + jlo);
            float4 v0 = __ldg(p4 + 0), v1 = __ldg(p4 + 1);
            xs[0]=v0.x; xs[1]=v0.y; xs[2]=v0.z; xs[3]=v0.w;
            xs[4]=v1.x; xs[5]=v1.y; xs[6]=v1.z; xs[7]=v1.w;
        } else {
            #pragma unroll
            for (int e = 0; e < 8; e++) {
                int j = jlo + e;
                xs[e] = (j >= 0 && j < T) ? __ldg(&xrow[j]) : 0.0f;
            }
        }
        #pragma unroll
        for (int e = 0; e < 8; e++)
            if (jlo + e > t0) xs[e] = 0.0f;      // future elems (lane 0 only)

        // ---- lane weight w = alpha * b^(8*lane) * b^(-e0), exact squaring ----
        float b8;
        { float b2 = b*b, b4 = b2*b2; b8 = b4*b4; }
        float w = alpha, q = b8;
        if (lane & 1)  w *= q;  q *= q;
        if (lane & 2)  w *= q;  q *= q;
        if (lane & 4)  w *= q;  q *= q;
        if (lane & 8)  w *= q;  q *= q;
        if (lane & 16) w *= q;
        float invb = __fdividef(1.0f, b);
        if (e0 & 1) w *= invb;
        if (e0 & 2) w *= invb * invb;

        // ---- weighted sum, descending j (w *= b per step) ----
        int ph_lo = jlo % slen; if (ph_lo < 0) ph_lo += slen;
        const float* inv_base = &sh_inv[wloc][ph_lo];
        #pragma unroll
        for (int k = 0; k < 8; k++) {
            int e = 7 - k;
            acc += (w * xs[e]) * inv_base[e];
            w *= b;
        }
    }

    // ---- full-warp xor reduce: every lane gets smooth_{t0} ----
    #pragma unroll
    for (int o = 16; o; o >>= 1)
        acc += __shfl_xor_sync(0xffffffffu, acc, o);

    // Initial-carry term only if the window reached the series start (cold).
    if (jend - WINDOW <= 0)
        acc += __powf(b, (float)(t0 + 1)) * __ldg(&xrow[0]);
    const float S0 = acc;

    // ---- NP predictions via closed-form warp prefix scan ----
    if (NP <= 16) {
        int p = lane;                        // lanes 0..NP-1 active
        float u = 0.0f, pb = 1.0f;
        int ph = 0;
        if (p < NP) {
            int t = t0 + 1 + p;
            ph = t % slen;
            float x = __ldg(&xrow[t]);       // coalesced
            float y = alpha * x * sh_inv[wloc][ph];
            // pb = b^p (4-bit exact-squaring build)
            float q = b;
            if (p & 1) pb *= q;  q *= q;
            if (p & 2) pb *= q;  q *= q;
            if (p & 4) pb *= q;  q *= q;
            if (p & 8) pb *= q;
            u = y * __fdividef(1.0f, pb);    // y * b^-p
        }
        // inclusive prefix sum over lanes (offsets 1,2,4,8 cover NP<=16)
        #pragma unroll
        for (int o = 1; o <= 8; o <<= 1) {
            float v = __shfl_up_sync(0xffffffffu, u, o);
            if (lane >= o) u += v;
        }
        if (p < NP) {
            float smooth = pb * (b * S0 + u);
            out[(size_t)row * NP + p] = smooth * sh_s[wloc][ph];
        }
    } else {
        // generic fallback: serial replay on lane 0
        if (lane == 0) {
            float smooth = S0;
            int ph = (t0 + 1) % slen;
            for (int p = 0; p < NP; p++) {
                float x = __ldg(&xrow[t0 + 1 + p]);
                smooth = alpha * x * sh_inv[wloc][ph] + b * smooth;
                out[(size_t)row * NP + p] = smooth * sh_s[wloc][ph];
                ph++; if (ph == slen) ph = 0;
            }
        }
    }
}

extern "C" void kernel_launch(void* const* d_in, const int* in_sizes, int n_in,
                              void* d_out, int out_size)
{
    const float* series      = (const float*)d_in[0];
    const int*   shifts      = (const int*)  d_in[1];
    const float* alpha_p     = (const float*)d_in[2];
    /* gamma (d_in[3]) unused by the reference */
    const float* init_season = (const float*)d_in[4];
    float* out = (float*)d_out;

    const int B    = in_sizes[1];
    const int T    = in_sizes[0] / B;
    const int slen = in_sizes[4];
    const int NP   = out_size / B;

    const int blocks = (B + WARPS_PER_BLOCK - 1) / WARPS_PER_BLOCK;
    hw_notrend_kernel<<<blocks, THREADS>>>(series, shifts, alpha_p, init_season,
                                           out, B, T, slen, NP);
}

// round 5
// speedup vs baseline: 1.3430x; 1.3430x over previous
#include <cuda_runtime.h>
#include <cuda_bf16.h>

// Holt-Winters (no trend), last n_preds columns only.
// smooth_t = a*(x_t/s_t) + b*smooth_{t-1}, b = 1-a; out_t = smooth_t * s_t.
// Closed form: smooth_{t0} = sum_j a*b^(t0-j)*(x_j/s_j) + b^(t0+1)*x_0.
// Terms older than the b^d < 1e-10 cutoff vanish in a float32 sum of O(1)
// terms; the sum is truncated to a window of <= 256 newest samples.
//
// One row per warp, 8 elements per lane (2 x LDG.128). Lane weights built by
// exact squaring (no powf). Seasonal reciprocals in a period-extended shared
// table. Kernel is TEMPLATED on SLEN so all %/÷ by the season length compile
// to magic-multiplies (SLEN_C==0 = generic runtime fallback).
// Final NP predictions via closed-form warp prefix scan (4 shfl_up).

#define WARPS_PER_BLOCK 8
#define THREADS (WARPS_PER_BLOCK * 32)
#define WINDOW 256
#define MAX_SLEN 16

template<int SLEN_C>
__global__ __launch_bounds__(THREADS)
void hw_notrend_kernel(const float* __restrict__ series,
                       const int*   __restrict__ shifts,
                       const float* __restrict__ alpha_p,
                       const float* __restrict__ init_season,
                       float*       __restrict__ out,
                       int B, int T, int slen_rt, int NP)
{
    const int sl = SLEN_C ? SLEN_C : slen_rt;   // compile-time when SLEN_C>0

    __shared__ float sh_inv[WARPS_PER_BLOCK][33];      // inv season, period-extended
    __shared__ float sh_s[WARPS_PER_BLOCK][MAX_SLEN];  // season values

    const int lane = threadIdx.x & 31;
    const int wloc = threadIdx.x >> 5;
    const int row  = blockIdx.x * WARPS_PER_BLOCK + wloc;
    if (row >= B) return;

    const float alpha = __ldg(alpha_p);
    const float b = 1.0f - alpha;

    // ---- per-row seasonal tables ----
    {
        int shift = __ldg(&shifts[row]);
        int ph  = lane % sl;
        int idx = ph - shift; idx %= sl; if (idx < 0) idx += sl;
        float sv = __ldg(&init_season[idx]);
        sh_inv[wloc][lane] = __fdividef(1.0f, sv);
        if (lane < sl) sh_s[wloc][lane] = sv;
        if (lane == 0) {
            int i32 = (32 % sl) - shift; i32 %= sl; if (i32 < 0) i32 += sl;
            sh_inv[wloc][32] = __fdividef(1.0f, __ldg(&init_season[i32]));
        }
    }
    __syncwarp();

    const int t0   = T - 1 - NP;                // target: smooth_{t0}
    const int jend = (t0 + 1 + 3) & ~3;         // align-up(t0+1, 4)
    const int e0   = jend - t0 - 1;             // 0..3
    const int jlo  = jend - 8 * (lane + 1);     // this lane's chunk (16B aligned)
    const int d0   = 8 * lane - e0;             // smallest age in chunk

    // Age cutoff: b^d < 1e-10  <=>  d > ln(1e-10)/ln(b)  (capped at WINDOW).
    const float lb = __logf(b);
    int dcut = WINDOW;
    if (lb < -1e-9f) {
        int c = (int)(-23.025851f / lb) + 1;
        if (c < dcut) dcut = c;
    }

    const float* __restrict__ xrow = series + (size_t)row * (size_t)T;
    const bool safe = (jend >= 8 * 32) && (jend <= T);   // warp-uniform

    float acc = 0.0f;
    if (d0 <= dcut) {
        float xs[8];
        if (safe) {
            const float4* p4 = (const float4*)(xrow + jlo);
            float4 v0 = __ldg(p4 + 0), v1 = __ldg(p4 + 1);
            xs[0]=v0.x; xs[1]=v0.y; xs[2]=v0.z; xs[3]=v0.w;
            xs[4]=v1.x; xs[5]=v1.y; xs[6]=v1.z; xs[7]=v1.w;
            if (lane == 0 && e0 > 0) {          // zero the <=3 future elements
                xs[7] = 0.0f;
                if (e0 > 1) xs[6] = 0.0f;
                if (e0 > 2) xs[5] = 0.0f;
            }
        } else {
            #pragma unroll
            for (int e = 0; e < 8; e++) {
                int j = jlo + e;
                xs[e] = (j >= 0 && j <= t0) ? __ldg(&xrow[j]) : 0.0f;
            }
        }

        // ---- lane weight w = alpha * b^(8*lane) * b^(-e0), exact squaring ----
        float b2 = b*b, b4 = b2*b2, b8 = b4*b4;
        float w = alpha, q = b8;
        if (lane & 1)  w *= q;  q *= q;
        if (lane & 2)  w *= q;  q *= q;
        if (lane & 4)  w *= q;  q *= q;
        if (lane & 8)  w *= q;  q *= q;
        if (lane & 16) w *= q;
        float invb = __fdividef(1.0f, b);
        if (e0 & 1) w *= invb;
        if (e0 & 2) w *= invb * invb;

        // ---- weighted sum, descending j (w *= b per step) ----
        int ph_lo = jlo % sl; if (ph_lo < 0) ph_lo += sl;
        const float* inv_base = &sh_inv[wloc][ph_lo];
        #pragma unroll
        for (int k = 0; k < 8; k++) {
            int e = 7 - k;
            acc += (w * xs[e]) * inv_base[e];   // LDS immediate offset
            w *= b;
        }
    }

    // ---- full-warp xor reduce: every lane gets smooth_{t0} ----
    #pragma unroll
    for (int o = 16; o; o >>= 1)
        acc += __shfl_xor_sync(0xffffffffu, acc, o);

    // Initial-carry term only if the window reached the series start (cold).
    if (jend - WINDOW <= 0)
        acc += __powf(b, (float)(t0 + 1)) * __ldg(&xrow[0]);
    const float S0 = acc;

    // ---- NP predictions via closed-form warp prefix scan ----
    if (NP <= 16) {
        const int p = lane;                      // lanes 0..NP-1 active
        float u = 0.0f, pb = 1.0f;
        int ph = 0;
        if (p < NP) {
            int t = t0 + 1 + p;
            ph = t % sl;
            float x = __ldg(&xrow[t]);           // coalesced
            float y = alpha * x * sh_inv[wloc][ph];
            float q = b;                         // pb = b^p
            if (p & 1) pb *= q;  q *= q;
            if (p & 2) pb *= q;  q *= q;
            if (p & 4) pb *= q;  q *= q;
            if (p & 8) pb *= q;
            u = y * __fdividef(1.0f, pb);        // y * b^-p
        }
        #pragma unroll
        for (int o = 1; o <= 8; o <<= 1) {       // inclusive prefix sum
            float v = __shfl_up_sync(0xffffffffu, u, o);
            if (lane >= o) u += v;
        }
        if (p < NP) {
            float smooth = pb * (b * S0 + u);
            out[(size_t)row * NP + p] = smooth * sh_s[wloc][ph];
        }
    } else {
        if (lane == 0) {                          // generic serial fallback
            float smooth = S0;
            int ph = (t0 + 1) % sl;
            for (int p = 0; p < NP; p++) {
                float x = __ldg(&xrow[t0 + 1 + p]);
                smooth = alpha * x * sh_inv[wloc][ph] + b * smooth;
                out[(size_t)row * NP + p] = smooth * sh_s[wloc][ph];
                ph++; if (ph == sl) ph = 0;
            }
        }
    }
}

extern "C" void kernel_launch(void* const* d_in, const int* in_sizes, int n_in,
                              void* d_out, int out_size)
{
    const float* series      = (const float*)d_in[0];
    const int*   shifts      = (const int*)  d_in[1];
    const float* alpha_p     = (const float*)d_in[2];
    /* gamma (d_in[3]) unused by the reference */
    const float* init_season = (const float*)d_in[4];
    float* out = (float*)d_out;

    const int B    = in_sizes[1];
    const int T    = in_sizes[0] / B;
    const int slen = in_sizes[4];
    const int NP   = out_size / B;

    const int blocks = (B + WARPS_PER_BLOCK - 1) / WARPS_PER_BLOCK;
    if (slen == 7)
        hw_notrend_kernel<7><<<blocks, THREADS>>>(series, shifts, alpha_p,
                                                  init_season, out, B, T, slen, NP);
    else
        hw_notrend_kernel<0><<<blocks, THREADS>>>(series, shifts, alpha_p,
                                                  init_season, out, B, T, slen, NP);
}